// round 11
// baseline (speedup 1.0000x reference)
#include <cuda_runtime.h>
#include <cuda_bf16.h>
#include <stdint.h>

#define B_DIM 128
#define C_DIM 2048
#define HW 196
#define NC 8
#define NM 4
#define NOUT 24                    // 8 A + 8 Z + 8 Y
#define PART_N (B_DIM * HW)        // 25088
#define SLABS 8
#define CSLAB (C_DIM / SLABS)      // 256
#define MPAD 208                   // 13 m16 tiles (196 real pixels + 12 pad)
#define WSTR 264                   // padded k-stride for W smem (bank-clean B frags)

// ---- scratch (__device__ globals; no allocation allowed) ----
__device__ float g_part[SLABS * NOUT * PART_N];   // 19.3 MB

// ---------------- mma helper: m16n8k16 bf16 x bf16 -> fp32 ----------------
__device__ __forceinline__ void mma_bf16(float* d, const uint32_t* a,
                                         const uint32_t* bb) {
    asm volatile(
        "mma.sync.aligned.m16n8k16.row.col.f32.bf16.bf16.f32 "
        "{%0,%1,%2,%3}, {%4,%5,%6,%7}, {%8,%9}, {%0,%1,%2,%3};"
        : "+f"(d[0]), "+f"(d[1]), "+f"(d[2]), "+f"(d[3])
        : "r"(a[0]), "r"(a[1]), "r"(a[2]), "r"(a[3]),
          "r"(bb[0]), "r"(bb[1]));
}

__device__ __forceinline__ void split_bf16(float v, __nv_bfloat16& h,
                                           __nv_bfloat16& l) {
    h = __float2bfloat16_rn(v);
    l = __float2bfloat16_rn(v - __bfloat162float(h));
}

// ============================================================================
// K1: tensor-core GEMM, one block per (batch, k-slab). 128 threads (4 warps).
//   D[px, o] += X[px, c] * W[c, o]  over c in the slab, o = 24 outputs
//   (o 0..7 = w_eff fold -> A/m_c pre-bias; 8..15 = w_cls lo -> Z;
//    16..23 = w_cls hi -> Y).
// bf16x3 split for ~fp32 accuracy. Partials -> g_part[slab][o][g].
// ============================================================================
__global__ void __launch_bounds__(128) k1_mma(
    const float* __restrict__ x,
    const float* __restrict__ w_down,
    const float* __restrict__ w_cls) {
    __shared__ __nv_bfloat16 Xh[MPAD * 16];       // [px][k16]
    __shared__ __nv_bfloat16 Xl[MPAD * 16];
    __shared__ __nv_bfloat16 Wh[NOUT * WSTR];     // [o][k256] padded stride
    __shared__ __nv_bfloat16 Wl[NOUT * WSTR];

    const int b = blockIdx.x;
    const int slab = blockIdx.y;
    const int t = threadIdx.x;
    const int lane = t & 31, w = t >> 5;
    const int gid = lane >> 2;        // groupID  (0..7)
    const int tig = lane & 3;         // thread-in-group (0..3)

    // ---- stage W slab: fold + bf16 split ----
    for (int i = t; i < NOUT * CSLAB; i += 128) {
        const int n = i >> 8;          // 0..23
        const int c = i & 255;
        const int cg = slab * CSLAB + c;
        float val;
        if (n < 8) {
            float s0 = w_down[(n * NM + 0) * C_DIM + cg];
            float s1 = w_down[(n * NM + 1) * C_DIM + cg];
            float s2 = w_down[(n * NM + 2) * C_DIM + cg];
            float s3 = w_down[(n * NM + 3) * C_DIM + cg];
            val = 0.25f * ((s0 + s1) + (s2 + s3));
        } else if (n < 16) {
            val = w_cls[(n - 8) * 2 * C_DIM + cg];
        } else {
            val = w_cls[(n - 16) * 2 * C_DIM + C_DIM + cg];
        }
        __nv_bfloat16 h, l;
        split_bf16(val, h, l);
        Wh[n * WSTR + c] = h;
        Wl[n * WSTR + c] = l;
    }
    // zero the 12 pad pixel-rows once (staging never writes rows >= 196)
    for (int i = t; i < (MPAD - HW) * 16; i += 128) {
        Xh[HW * 16 + i] = __float2bfloat16_rn(0.f);
        Xl[HW * 16 + i] = __float2bfloat16_rn(0.f);
    }
    __syncthreads();

    // accumulators: warp w owns m-tiles {w, w+4, w+8 (, 12 for w==0)}
    const int nmt = (w == 0) ? 4 : 3;
    float acc[4][3][4];
#pragma unroll
    for (int i = 0; i < 4; ++i)
#pragma unroll
        for (int nt = 0; nt < 3; ++nt)
#pragma unroll
            for (int r = 0; r < 4; ++r) acc[i][nt][r] = 0.f;

    const float* xb = x + ((size_t)b * C_DIM + slab * CSLAB) * HW;

#pragma unroll 1
    for (int kc = 0; kc < 16; ++kc) {
        // ---- stage X chunk: gmem [16 ch][196 px fp32] -> smem [px][16] split
        const float4* xc = (const float4*)(xb + (size_t)kc * 16 * HW);
#pragma unroll 1
        for (int i = t; i < 16 * 49; i += 128) {
            const int j = i / 49;            // channel 0..15
            const int q = i - j * 49;        // float4 index in pixel row
            float4 v = xc[j * 49 + q];
            const int px = q * 4;
            __nv_bfloat16 h, l;
            split_bf16(v.x, h, l); Xh[(px + 0) * 16 + j] = h; Xl[(px + 0) * 16 + j] = l;
            split_bf16(v.y, h, l); Xh[(px + 1) * 16 + j] = h; Xl[(px + 1) * 16 + j] = l;
            split_bf16(v.z, h, l); Xh[(px + 2) * 16 + j] = h; Xl[(px + 2) * 16 + j] = l;
            split_bf16(v.w, h, l); Xh[(px + 3) * 16 + j] = h; Xl[(px + 3) * 16 + j] = l;
        }
        __syncthreads();

        // ---- B fragments for this k-chunk (3 n-tiles, hi+lo) ----
        uint32_t bh[3][2], bl[3][2];
#pragma unroll
        for (int nt = 0; nt < 3; ++nt) {
            const int n = nt * 8 + gid;
            const int kb = kc * 16 + 2 * tig;
            bh[nt][0] = *(const uint32_t*)&Wh[n * WSTR + kb];
            bh[nt][1] = *(const uint32_t*)&Wh[n * WSTR + kb + 8];
            bl[nt][0] = *(const uint32_t*)&Wl[n * WSTR + kb];
            bl[nt][1] = *(const uint32_t*)&Wl[n * WSTR + kb + 8];
        }

        // ---- A fragments + mma per m-tile ----
#pragma unroll
        for (int i = 0; i < 4; ++i) {
            if (i >= nmt) break;
            const int mt = w + 4 * i;
            const int r0 = mt * 16 + gid;
            const int kb = 2 * tig;
            uint32_t ah[4], al[4];
            ah[0] = *(const uint32_t*)&Xh[r0 * 16 + kb];
            ah[1] = *(const uint32_t*)&Xh[(r0 + 8) * 16 + kb];
            ah[2] = *(const uint32_t*)&Xh[r0 * 16 + kb + 8];
            ah[3] = *(const uint32_t*)&Xh[(r0 + 8) * 16 + kb + 8];
            al[0] = *(const uint32_t*)&Xl[r0 * 16 + kb];
            al[1] = *(const uint32_t*)&Xl[(r0 + 8) * 16 + kb];
            al[2] = *(const uint32_t*)&Xl[r0 * 16 + kb + 8];
            al[3] = *(const uint32_t*)&Xl[(r0 + 8) * 16 + kb + 8];
#pragma unroll
            for (int nt = 0; nt < 3; ++nt) {
                mma_bf16(acc[i][nt], ah, bh[nt]);   // xh*wh
                mma_bf16(acc[i][nt], ah, bl[nt]);   // xh*wl
                mma_bf16(acc[i][nt], al, bh[nt]);   // xl*wh
            }
        }
        __syncthreads();   // X buffer reused next chunk
    }

    // ---- writeback: D rows = pixels, cols = outputs ----
#pragma unroll
    for (int i = 0; i < 4; ++i) {
        if (i >= nmt) break;
        const int mt = w + 4 * i;
        const int px0 = mt * 16 + gid;
        const int px1 = px0 + 8;
#pragma unroll
        for (int nt = 0; nt < 3; ++nt) {
            const int o = nt * 8 + 2 * tig;
            float* base = g_part + ((size_t)slab * NOUT + o) * PART_N
                        + (size_t)b * HW;
            if (px0 < HW) {
                base[px0] = acc[i][nt][0];
                base[PART_N + px0] = acc[i][nt][1];
            }
            if (px1 < HW) {
                base[px1] = acc[i][nt][2];
                base[PART_N + px1] = acc[i][nt][3];
            }
        }
    }
}

// ============================================================================
// K2a: per (k, b) block: m_c[b,k,p] = sum_s A_part + beff[k] -> out_mc;
//      v[b,k] = mean_p m_c -> out_v.   grid (8, 128) x 224 threads.
// ============================================================================
__global__ void __launch_bounds__(224) k2a(
    const float* __restrict__ b_down,
    float* __restrict__ out_v,
    float* __restrict__ out_mc) {
    __shared__ float wpart[7];
    const int k = blockIdx.x;
    const int b = blockIdx.y;
    const int t = threadIdx.x;
    const int g0 = b * HW;

    float mc = 0.f;
    if (t < HW) {
        float a[SLABS];
#pragma unroll
        for (int s = 0; s < SLABS; ++s)
            a[s] = g_part[((size_t)s * NOUT + k) * PART_N + g0 + t];
        float sum = ((a[0] + a[1]) + (a[2] + a[3])) +
                    ((a[4] + a[5]) + (a[6] + a[7]));
        float beff = 0.25f * ((b_down[4 * k] + b_down[4 * k + 1]) +
                              (b_down[4 * k + 2] + b_down[4 * k + 3]));
        mc = sum + beff;
        out_mc[((size_t)b * NC + k) * HW + t] = mc;
    }
    float s = mc;
#pragma unroll
    for (int o = 16; o; o >>= 1) s += __shfl_down_sync(0xffffffffu, s, o);
    const int lane = t & 31, warp = t >> 5;
    if (lane == 0) wpart[warp] = s;
    __syncthreads();
    if (t == 0) {
        float tot = 0.f;
#pragma unroll
        for (int w = 0; w < 7; ++w) tot += wpart[w];
        out_v[b * NC + k] = tot * (1.0f / (float)HW);
    }
}

// ============================================================================
// K2b: m[b,p] = (1/NC) sum_k v[b,k]*m_c[b,k,p].  grid 128 x 224.
// ============================================================================
__global__ void __launch_bounds__(224) k2b(
    const float* __restrict__ v_in,
    const float* __restrict__ mc_in,
    float* __restrict__ out_m) {
    __shared__ float vsh[NC];
    const int b = blockIdx.x;
    const int t = threadIdx.x;
    if (t < NC) vsh[t] = v_in[b * NC + t];
    __syncthreads();
    if (t < HW) {
        float a[NC];
#pragma unroll
        for (int k = 0; k < NC; ++k)
            a[k] = mc_in[((size_t)b * NC + k) * HW + t];
        float m = 0.f;
#pragma unroll
        for (int k = 0; k < NC; ++k) m = fmaf(vsh[k], a[k], m);
        out_m[b * HW + t] = m * (1.0f / (float)NC);
    }
}

// ============================================================================
// K2c: output[b,k] = (1/HW) sum_p (Z[k,p] + m[p]*Y[k,p]) + b_cls[k].
// grid (8, 128) x 224 threads.
// ============================================================================
__global__ void __launch_bounds__(224) k2c(
    const float* __restrict__ m_in,
    const float* __restrict__ b_cls,
    float* __restrict__ out_output) {
    __shared__ float wpart[7];
    const int k = blockIdx.x;
    const int b = blockIdx.y;
    const int t = threadIdx.x;
    const int g0 = b * HW;

    float po = 0.f;
    if (t < HW) {
        float z[SLABS], y[SLABS];
#pragma unroll
        for (int s = 0; s < SLABS; ++s)
            z[s] = g_part[((size_t)s * NOUT + 8 + k) * PART_N + g0 + t];
#pragma unroll
        for (int s = 0; s < SLABS; ++s)
            y[s] = g_part[((size_t)s * NOUT + 16 + k) * PART_N + g0 + t];
        float m = m_in[b * HW + t];
        float zs = ((z[0] + z[1]) + (z[2] + z[3])) +
                   ((z[4] + z[5]) + (z[6] + z[7]));
        float ys = ((y[0] + y[1]) + (y[2] + y[3])) +
                   ((y[4] + y[5]) + (y[6] + y[7]));
        po = fmaf(m, ys, zs);
    }
    float s = po;
#pragma unroll
    for (int o = 16; o; o >>= 1) s += __shfl_down_sync(0xffffffffu, s, o);
    const int lane = t & 31, warp = t >> 5;
    if (lane == 0) wpart[warp] = s;
    __syncthreads();
    if (t == 0) {
        float tot = 0.f;
#pragma unroll
        for (int w = 0; w < 7; ++w) tot += wpart[w];
        out_output[b * NC + k] = tot * (1.0f / (float)HW) + b_cls[k];
    }
}

// ============================================================================
// kernel_launch: 4 launches, graph-capturable, deterministic.
// Output layout: v[128,8]@0, output[128,8]@1024, m[128,196]@2048,
//                m_c[128,8,196]@27136.
// ============================================================================
extern "C" void kernel_launch(void* const* d_in, const int* in_sizes, int n_in,
                              void* d_out, int out_size) {
    const float* x      = (const float*)d_in[0];
    const float* w_down = (const float*)d_in[1];
    const float* b_down = (const float*)d_in[2];
    const float* w_cls  = (const float*)d_in[3];
    const float* b_cls  = (const float*)d_in[4];

    float* out        = (float*)d_out;
    float* out_v      = out;
    float* out_output = out + 1024;
    float* out_m      = out + 2048;
    float* out_mc     = out + 27136;

    k1_mma<<<dim3(B_DIM, SLABS), 128>>>(x, w_down, w_cls);
    k2a<<<dim3(NC, B_DIM), 224>>>(b_down, out_v, out_mc);
    k2b<<<B_DIM, 224>>>(out_v, out_mc, out_m);
    k2c<<<dim3(NC, B_DIM), 224>>>(out_m, b_cls, out_output);
}

// round 12
// speedup vs baseline: 3.1761x; 3.1761x over previous
#include <cuda_runtime.h>
#include <cuda_bf16.h>
#include <stdint.h>

#define B_DIM 128
#define C_DIM 2048
#define HW 196
#define NC 8
#define NM 4
#define NOUT 24                    // 8 A + 8 Z + 8 Y
#define PART_N (B_DIM * HW)        // 25088
#define SLABS 8
#define CSLAB (C_DIM / SLABS)      // 256
#define WSTR 264                   // padded k-stride for W smem (bank-clean)

// ---- scratch (__device__ globals; no allocation allowed) ----
__device__ float g_part[SLABS * NOUT * PART_N];   // 19.3 MB

// ---------------- mma helper: m16n8k16 bf16 x bf16 -> fp32 ----------------
__device__ __forceinline__ void mma_bf16(float* d, const uint32_t* a,
                                         const uint32_t* bb) {
    asm volatile(
        "mma.sync.aligned.m16n8k16.row.col.f32.bf16.bf16.f32 "
        "{%0,%1,%2,%3}, {%4,%5,%6,%7}, {%8,%9}, {%0,%1,%2,%3};"
        : "+f"(d[0]), "+f"(d[1]), "+f"(d[2]), "+f"(d[3])
        : "r"(a[0]), "r"(a[1]), "r"(a[2]), "r"(a[3]),
          "r"(bb[0]), "r"(bb[1]));
}

// pack two fp32 into bf16x2: low half = lo, high half = hi
__device__ __forceinline__ uint32_t pack_bf16x2(float lo, float hi) {
    uint32_t r;
    asm("cvt.rn.bf16x2.f32 %0, %1, %2;" : "=r"(r) : "f"(hi), "f"(lo));
    return r;
}

// split (x0, x1) into hi bf16x2 + residual-lo bf16x2 (in registers, no smem)
__device__ __forceinline__ void split2(float x0, float x1,
                                       uint32_t& h, uint32_t& l) {
    h = pack_bf16x2(x0, x1);
    float h0 = __uint_as_float(h << 16);
    float h1 = __uint_as_float(h & 0xffff0000u);
    l = pack_bf16x2(x0 - h0, x1 - h1);
}

__device__ __forceinline__ void split_w(float v, __nv_bfloat16& h,
                                        __nv_bfloat16& l) {
    h = __float2bfloat16_rn(v);
    l = __float2bfloat16_rn(v - __bfloat162float(h));
}

// ============================================================================
// K1: tensor-core GEMM, one block per (batch, k-slab). 128 threads (4 warps).
//   D[px, o] += X[px, c] * W[c, o], o = 24 outputs
//   (0..7 w_eff fold -> A; 8..15 w_cls lo -> Z; 16..23 w_cls hi -> Y).
// A fragments loaded DIRECTLY from gmem in fragment layout (4 full 32B
// sectors per warp-load, no smem staging, no syncs in the main loop);
// bf16x3 split in registers. W slab staged once in smem (conflict-free).
// Writeback identical to the verified round-11 mapping.
// ============================================================================
__global__ void __launch_bounds__(128) k1_mma(
    const float* __restrict__ x,
    const float* __restrict__ w_down,
    const float* __restrict__ w_cls) {
    __shared__ __nv_bfloat16 Wh[NOUT * WSTR];     // [o][k256] padded stride
    __shared__ __nv_bfloat16 Wl[NOUT * WSTR];

    const int b = blockIdx.x;
    const int slab = blockIdx.y;
    const int t = threadIdx.x;
    const int lane = t & 31, w = t >> 5;
    const int gid = lane >> 2;        // groupID  (0..7)
    const int tig = lane & 3;         // thread-in-group (0..3)

    // ---- stage W slab: fold + bf16 split (once) ----
    for (int i = t; i < NOUT * CSLAB; i += 128) {
        const int n = i >> 8;          // 0..23
        const int c = i & 255;
        const int cg = slab * CSLAB + c;
        float val;
        if (n < 8) {
            float s0 = w_down[(n * NM + 0) * C_DIM + cg];
            float s1 = w_down[(n * NM + 1) * C_DIM + cg];
            float s2 = w_down[(n * NM + 2) * C_DIM + cg];
            float s3 = w_down[(n * NM + 3) * C_DIM + cg];
            val = 0.25f * ((s0 + s1) + (s2 + s3));
        } else if (n < 16) {
            val = w_cls[(n - 8) * 2 * C_DIM + cg];
        } else {
            val = w_cls[(n - 16) * 2 * C_DIM + C_DIM + cg];
        }
        __nv_bfloat16 h, l;
        split_w(val, h, l);
        Wh[n * WSTR + c] = h;
        Wl[n * WSTR + c] = l;
    }
    __syncthreads();

    // warp w owns m-tiles {w, w+4, w+8} (+12 for w==0); 13 tiles cover 208>=196
    const int nmt = (w == 0) ? 4 : 3;
    float acc[4][3][4];
#pragma unroll
    for (int i = 0; i < 4; ++i)
#pragma unroll
        for (int nt = 0; nt < 3; ++nt)
#pragma unroll
            for (int r = 0; r < 4; ++r) acc[i][nt][r] = 0.f;

    const float* xb = x + ((size_t)b * C_DIM + slab * CSLAB) * HW;

#pragma unroll 1
    for (int kc = 0; kc < CSLAB / 16; ++kc) {
        // ---- B fragments for this k-chunk (3 n-tiles, hi+lo) ----
        uint32_t bh[3][2], bl[3][2];
        const int kb = kc * 16 + 2 * tig;
#pragma unroll
        for (int nt = 0; nt < 3; ++nt) {
            const int n = nt * 8 + gid;
            bh[nt][0] = *(const uint32_t*)&Wh[n * WSTR + kb];
            bh[nt][1] = *(const uint32_t*)&Wh[n * WSTR + kb + 8];
            bl[nt][0] = *(const uint32_t*)&Wl[n * WSTR + kb];
            bl[nt][1] = *(const uint32_t*)&Wl[n * WSTR + kb + 8];
        }

        // channel rows for this thread: c0 = kc*16 + 2*tig (+0,1,8,9)
        const float* r0 = xb + (size_t)(kc * 16 + 2 * tig) * HW;

#pragma unroll
        for (int i = 0; i < 4; ++i) {
            if (i >= nmt) break;
            const int mt = w + 4 * i;
            const int p0 = mt * 16 + gid;
            const int p1 = p0 + 8;

            float f0, f1, f2, f3, f4, f5, f6, f7;
            if (i < 3) {   // full tiles: unguarded loads
                f0 = r0[p0];            f1 = r0[HW + p0];
                f2 = r0[p1];            f3 = r0[HW + p1];
                f4 = r0[8 * HW + p0];   f5 = r0[9 * HW + p0];
                f6 = r0[8 * HW + p1];   f7 = r0[9 * HW + p1];
            } else {       // tile 12: pixels 192..207, guard >=196
                bool g0v = (p0 < HW);
                f0 = g0v ? r0[p0] : 0.f;
                f1 = g0v ? r0[HW + p0] : 0.f;
                f4 = g0v ? r0[8 * HW + p0] : 0.f;
                f5 = g0v ? r0[9 * HW + p0] : 0.f;
                f2 = 0.f; f3 = 0.f; f6 = 0.f; f7 = 0.f;   // p1 >= 200 always
            }

            uint32_t ah[4], al[4];
            split2(f0, f1, ah[0], al[0]);   // row p0, k kb..kb+1
            split2(f2, f3, ah[1], al[1]);   // row p1, k kb..kb+1
            split2(f4, f5, ah[2], al[2]);   // row p0, k kb+8..kb+9
            split2(f6, f7, ah[3], al[3]);   // row p1, k kb+8..kb+9

#pragma unroll
            for (int nt = 0; nt < 3; ++nt) {
                mma_bf16(acc[i][nt], ah, bh[nt]);   // xh*wh
                mma_bf16(acc[i][nt], ah, bl[nt]);   // xh*wl
                mma_bf16(acc[i][nt], al, bh[nt]);   // xl*wh
            }
        }
    }

    // ---- writeback (verified round-11 mapping) ----
#pragma unroll
    for (int i = 0; i < 4; ++i) {
        if (i >= nmt) break;
        const int mt = w + 4 * i;
        const int px0 = mt * 16 + gid;
        const int px1 = px0 + 8;
#pragma unroll
        for (int nt = 0; nt < 3; ++nt) {
            const int o = nt * 8 + 2 * tig;
            float* base = g_part + ((size_t)slab * NOUT + o) * PART_N
                        + (size_t)b * HW;
            if (px0 < HW) {
                base[px0] = acc[i][nt][0];
                base[PART_N + px0] = acc[i][nt][1];
            }
            if (px1 < HW) {
                base[px1] = acc[i][nt][2];
                base[PART_N + px1] = acc[i][nt][3];
            }
        }
    }
}

// ============================================================================
// K2a: per (k, b) block: m_c[b,k,p] = sum_s A_part + beff[k] -> out_mc;
//      v[b,k] = mean_p m_c -> out_v.   grid (8, 128) x 224 threads.
// ============================================================================
__global__ void __launch_bounds__(224) k2a(
    const float* __restrict__ b_down,
    float* __restrict__ out_v,
    float* __restrict__ out_mc) {
    __shared__ float wpart[7];
    const int k = blockIdx.x;
    const int b = blockIdx.y;
    const int t = threadIdx.x;
    const int g0 = b * HW;

    float mc = 0.f;
    if (t < HW) {
        float a[SLABS];
#pragma unroll
        for (int s = 0; s < SLABS; ++s)
            a[s] = g_part[((size_t)s * NOUT + k) * PART_N + g0 + t];
        float sum = ((a[0] + a[1]) + (a[2] + a[3])) +
                    ((a[4] + a[5]) + (a[6] + a[7]));
        float beff = 0.25f * ((b_down[4 * k] + b_down[4 * k + 1]) +
                              (b_down[4 * k + 2] + b_down[4 * k + 3]));
        mc = sum + beff;
        out_mc[((size_t)b * NC + k) * HW + t] = mc;
    }
    float s = mc;
#pragma unroll
    for (int o = 16; o; o >>= 1) s += __shfl_down_sync(0xffffffffu, s, o);
    const int lane = t & 31, warp = t >> 5;
    if (lane == 0) wpart[warp] = s;
    __syncthreads();
    if (t == 0) {
        float tot = 0.f;
#pragma unroll
        for (int w = 0; w < 7; ++w) tot += wpart[w];
        out_v[b * NC + k] = tot * (1.0f / (float)HW);
    }
}

// ============================================================================
// K2b: m[b,p] = (1/NC) sum_k v[b,k]*m_c[b,k,p].  grid 128 x 224.
// ============================================================================
__global__ void __launch_bounds__(224) k2b(
    const float* __restrict__ v_in,
    const float* __restrict__ mc_in,
    float* __restrict__ out_m) {
    __shared__ float vsh[NC];
    const int b = blockIdx.x;
    const int t = threadIdx.x;
    if (t < NC) vsh[t] = v_in[b * NC + t];
    __syncthreads();
    if (t < HW) {
        float a[NC];
#pragma unroll
        for (int k = 0; k < NC; ++k)
            a[k] = mc_in[((size_t)b * NC + k) * HW + t];
        float m = 0.f;
#pragma unroll
        for (int k = 0; k < NC; ++k) m = fmaf(vsh[k], a[k], m);
        out_m[b * HW + t] = m * (1.0f / (float)NC);
    }
}

// ============================================================================
// K2c: output[b,k] = (1/HW) sum_p (Z[k,p] + m[p]*Y[k,p]) + b_cls[k].
// grid (8, 128) x 224 threads.
// ============================================================================
__global__ void __launch_bounds__(224) k2c(
    const float* __restrict__ m_in,
    const float* __restrict__ b_cls,
    float* __restrict__ out_output) {
    __shared__ float wpart[7];
    const int k = blockIdx.x;
    const int b = blockIdx.y;
    const int t = threadIdx.x;
    const int g0 = b * HW;

    float po = 0.f;
    if (t < HW) {
        float z[SLABS], y[SLABS];
#pragma unroll
        for (int s = 0; s < SLABS; ++s)
            z[s] = g_part[((size_t)s * NOUT + 8 + k) * PART_N + g0 + t];
#pragma unroll
        for (int s = 0; s < SLABS; ++s)
            y[s] = g_part[((size_t)s * NOUT + 16 + k) * PART_N + g0 + t];
        float m = m_in[b * HW + t];
        float zs = ((z[0] + z[1]) + (z[2] + z[3])) +
                   ((z[4] + z[5]) + (z[6] + z[7]));
        float ys = ((y[0] + y[1]) + (y[2] + y[3])) +
                   ((y[4] + y[5]) + (y[6] + y[7]));
        po = fmaf(m, ys, zs);
    }
    float s = po;
#pragma unroll
    for (int o = 16; o; o >>= 1) s += __shfl_down_sync(0xffffffffu, s, o);
    const int lane = t & 31, warp = t >> 5;
    if (lane == 0) wpart[warp] = s;
    __syncthreads();
    if (t == 0) {
        float tot = 0.f;
#pragma unroll
        for (int w = 0; w < 7; ++w) tot += wpart[w];
        out_output[b * NC + k] = tot * (1.0f / (float)HW) + b_cls[k];
    }
}

// ============================================================================
// kernel_launch: 4 launches, graph-capturable, deterministic.
// Output layout: v[128,8]@0, output[128,8]@1024, m[128,196]@2048,
//                m_c[128,8,196]@27136.
// ============================================================================
extern "C" void kernel_launch(void* const* d_in, const int* in_sizes, int n_in,
                              void* d_out, int out_size) {
    const float* x      = (const float*)d_in[0];
    const float* w_down = (const float*)d_in[1];
    const float* b_down = (const float*)d_in[2];
    const float* w_cls  = (const float*)d_in[3];
    const float* b_cls  = (const float*)d_in[4];

    float* out        = (float*)d_out;
    float* out_v      = out;
    float* out_output = out + 1024;
    float* out_m      = out + 2048;
    float* out_mc     = out + 27136;

    k1_mma<<<dim3(B_DIM, SLABS), 128>>>(x, w_down, w_cls);
    k2a<<<dim3(NC, B_DIM), 224>>>(b_down, out_v, out_mc);
    k2b<<<B_DIM, 224>>>(out_v, out_mc, out_m);
    k2c<<<dim3(NC, B_DIM), 224>>>(out_m, b_cls, out_output);
}